// round 17
// baseline (speedup 1.0000x reference)
#include <cuda_runtime.h>
#include <cuda_bf16.h>
#include <cstdint>

#define D 128
#define D4 32
#define N_MAX 50000
#define LN_EPS 1e-5f
#define TILE_M 64
#define GEMM_CTAS 296

// ---------------- device globals ----------------
__device__ float g_agg[(size_t)N_MAX * D];
__device__ int   g_tile_ctr;
__device__ __nv_bfloat16 g_whi[128 * 128];   // W hi, swizzled image
__device__ __nv_bfloat16 g_wlo[128 * 128];   // W lo, swizzled image

// smem offsets (from 1024-aligned dynamic base)
#define OFF_A_HI   0          // 16 KB (64 rows x 256B)
#define OFF_A_LO   16384
#define OFF_B_HI   32768      // 32 KB (128 rows x 256B)
#define OFF_B_LO   65536
#define OFF_BIAS   98304
#define OFF_GAMMA  98816
#define OFF_BETA   99328
#define OFF_SPART  99840      // float[2][64]
#define OFF_QPART  100352     // float[2][64]
#define OFF_TILE   100864
#define SMEM_TOTAL (100868 + 1040)

// Swizzled byte offset of 16B chunk c (0..15) in row `row` (256B rows).
__host__ __device__ __forceinline__ uint32_t swz16(int row, int c) {
    return (uint32_t)(row * 256 + ((c ^ (row & 7)) << 4));
}

__device__ __forceinline__ uint32_t smem_u32(const void* p) {
    uint32_t a;
    asm("{ .reg .u64 t; cvta.to.shared.u64 t, %1; cvt.u32.u64 %0, t; }" : "=r"(a) : "l"(p));
    return a;
}
// packed bf16x2: high = rn(f1), low = rn(f0)
__device__ __forceinline__ uint32_t pack_bf2(float f0, float f1) {
    uint32_t r;
    asm("cvt.rn.bf16x2.f32 %0, %1, %2;" : "=r"(r) : "f"(f1), "f"(f0));
    return r;
}

// ---------------------------------------------------------------------------
// Kernel 1: agg = h  (+ tile counter reset)
// ---------------------------------------------------------------------------
__global__ void k_init_agg(const float4* __restrict__ h4, int n4) {
    int i = blockIdx.x * blockDim.x + threadIdx.x;
    if (i == 0) g_tile_ctr = 0;
    float4* agg4 = reinterpret_cast<float4*>(g_agg);
    if (i < n4) agg4[i] = h4[i];
}

// ---------------------------------------------------------------------------
// Kernel 2: W -> hi/lo bf16 swizzled global images
// ---------------------------------------------------------------------------
__global__ void k_prep_w(const float* __restrict__ W) {
    int t = blockIdx.x * blockDim.x + threadIdx.x;
    for (int idx = t; idx < 128 * 128; idx += blockDim.x * gridDim.x) {
        int n = idx >> 7, k = idx & 127;
        float w = W[idx];
        __nv_bfloat16 hi = __float2bfloat16_rn(w);
        __nv_bfloat16 lo = __float2bfloat16_rn(w - __bfloat162float(hi));
        uint32_t o = (swz16(n, k >> 3) + ((k & 7) << 1)) >> 1;
        g_whi[o] = hi;
        g_wlo[o] = lo;
    }
}

// ---------------------------------------------------------------------------
// Kernel 3: vectorized scatter (at LTS byte-throughput floor)
// ---------------------------------------------------------------------------
__global__ __launch_bounds__(256)
void k_scatter_v4(const float4* __restrict__ h4,
                  const int* __restrict__ src,
                  const int* __restrict__ dst,
                  int E) {
    int warp_id = (blockIdx.x * blockDim.x + threadIdx.x) >> 5;
    int lane = threadIdx.x & 31;
    if (warp_id >= E) return;
    int s = __ldg(src + warp_id);
    int d = __ldg(dst + warp_id);
    float4 v = h4[(size_t)s * D4 + lane];
    float4* ap = reinterpret_cast<float4*>(g_agg) + (size_t)d * D4 + lane;
    asm volatile("red.global.add.v4.f32 [%0], {%1, %2, %3, %4};"
                 :: "l"(ap), "f"(v.x), "f"(v.y), "f"(v.z), "f"(v.w) : "memory");
}

// ---------------------------------------------------------------------------
// Kernel 4: HMMA GEMM (hi/lo bf16, 3 passes) + bias + LN + ReLU
// TILE_M=64, 2 CTAs/SM, 8 warps: wid&3 = row group (16 rows),
// wid>>2 = col half (64 cols). acc = 8 nt x 4 = 32 regs.
// ---------------------------------------------------------------------------
extern __shared__ char dsmem[];
__global__ __launch_bounds__(256, 2)
void k_mma_gemm(const float* __restrict__ bias,
                const float* __restrict__ gamma,
                const float* __restrict__ beta,
                float* __restrict__ out,
                int N) {
    uint32_t raw = smem_u32(dsmem);
    char* base = dsmem + ((1024 - (raw & 1023)) & 1023);
    const uint32_t sb = smem_u32(base);

    const int t = threadIdx.x;
    const int wid = t >> 5;
    const int lane = t & 31;

    // one-time: W images + vectors into smem
    {
        const uint4* whi4 = reinterpret_cast<const uint4*>(g_whi);
        const uint4* wlo4 = reinterpret_cast<const uint4*>(g_wlo);
        uint4* bhi4 = reinterpret_cast<uint4*>(base + OFF_B_HI);
        uint4* blo4 = reinterpret_cast<uint4*>(base + OFF_B_LO);
        for (int i = t; i < 2048; i += 256) { bhi4[i] = whi4[i]; blo4[i] = wlo4[i]; }
        float* sbi_w = reinterpret_cast<float*>(base + OFF_BIAS);
        float* sga_w = reinterpret_cast<float*>(base + OFF_GAMMA);
        float* sbe_w = reinterpret_cast<float*>(base + OFF_BETA);
        if (t < 128) { sbi_w[t] = bias[t]; sga_w[t] = gamma[t]; sbe_w[t] = beta[t]; }
    }

    int* s_tl = reinterpret_cast<int*>(base + OFF_TILE);
    const float* sbi = reinterpret_cast<const float*>(base + OFF_BIAS);
    const float* sga = reinterpret_cast<const float*>(base + OFF_GAMMA);
    const float* sbe = reinterpret_cast<const float*>(base + OFF_BETA);
    float* s_s = reinterpret_cast<float*>(base + OFF_SPART);   // [2][64]
    float* s_q = reinterpret_cast<float*>(base + OFF_QPART);

    // warp geometry
    const int wg = wid & 3;            // row group: rows [wg*16, wg*16+16)
    const int ch = wid >> 2;           // col half:  cols [ch*64, ch*64+64)
    const int l7   = lane & 7;
    const int bsel = (lane >> 3) & 1;
    const int arow = wg * 16 + (bsel << 3) + l7;
    const uint32_t arow_off = (uint32_t)arow * 256;
    const int a_r7 = arow & 7;
    const int aksel = lane >> 4;
    const uint32_t brow_off = (uint32_t)l7 * 256;
    const int qlane = lane & 3;
    const int rowA = wg * 16 + (lane >> 2);   // row within tile (B row = +8)

    const int numTiles = (N + TILE_M - 1) / TILE_M;

    for (;;) {
        if (t == 0) *s_tl = atomicAdd(&g_tile_ctr, 1);
        __syncthreads();
        const int tile = *s_tl;
        if (tile >= numTiles) break;
        const int base_row = tile * TILE_M;

        // ---- stage A: 64 rows -> bf16 hi/lo, swizzled ----
        {
            const int row = t >> 2;           // 0..63
            const int kq = t & 3;             // quarter: chunks [kq*4, kq*4+4)
            int gr = base_row + row; if (gr >= N) gr = N - 1;
            const float4* xr = reinterpret_cast<const float4*>(g_agg + (size_t)gr * 128) + kq * 8;
            char* Ah = base + OFF_A_HI;
            char* Al = base + OFF_A_LO;
#pragma unroll
            for (int i = 0; i < 4; i++) {
                float4 u = xr[i * 2];
                float4 v = xr[i * 2 + 1];
                uint32_t hp0 = pack_bf2(u.x, u.y);
                uint32_t hp1 = pack_bf2(u.z, u.w);
                uint32_t hp2 = pack_bf2(v.x, v.y);
                uint32_t hp3 = pack_bf2(v.z, v.w);
                uint32_t lp0 = pack_bf2(u.x - __uint_as_float(hp0 << 16),
                                        u.y - __uint_as_float(hp0 & 0xffff0000u));
                uint32_t lp1 = pack_bf2(u.z - __uint_as_float(hp1 << 16),
                                        u.w - __uint_as_float(hp1 & 0xffff0000u));
                uint32_t lp2 = pack_bf2(v.x - __uint_as_float(hp2 << 16),
                                        v.y - __uint_as_float(hp2 & 0xffff0000u));
                uint32_t lp3 = pack_bf2(v.z - __uint_as_float(hp3 << 16),
                                        v.w - __uint_as_float(hp3 & 0xffff0000u));
                uint32_t off = swz16(row, kq * 4 + i);
                *reinterpret_cast<uint4*>(Ah + off) = make_uint4(hp0, hp1, hp2, hp3);
                *reinterpret_cast<uint4*>(Al + off) = make_uint4(lp0, lp1, lp2, lp3);
            }
        }
        __syncthreads();

        // ---- 3-pass MMA: D = Ah*Bh + Ah*Bl + Al*Bh ----
        float acc[8][4];
#pragma unroll
        for (int nt = 0; nt < 8; nt++)
            acc[nt][0] = acc[nt][1] = acc[nt][2] = acc[nt][3] = 0.f;

#pragma unroll
        for (int pass = 0; pass < 3; pass++) {
            const uint32_t SA = sb + ((pass == 2) ? OFF_A_LO : OFF_A_HI);
            const uint32_t SB = sb + ((pass == 1) ? OFF_B_LO : OFF_B_HI);
#pragma unroll
            for (int ks = 0; ks < 8; ks++) {
                uint32_t a0, a1, a2, a3;
                {
                    int ac = ks * 2 + aksel;
                    uint32_t aaddr = SA + arow_off + (uint32_t)((ac ^ a_r7) << 4);
                    asm volatile("ldmatrix.sync.aligned.m8n8.x4.shared.b16 {%0,%1,%2,%3}, [%4];"
                                 : "=r"(a0), "=r"(a1), "=r"(a2), "=r"(a3) : "r"(aaddr));
                }
                const uint32_t bx = (uint32_t)(((ks * 2 + bsel) ^ l7) << 4);
#pragma unroll
                for (int nt = 0; nt < 8; nt++) {
                    uint32_t b0, b1;
                    uint32_t baddr = SB + (uint32_t)((ch * 8 + nt) * 2048) + brow_off + bx;
                    asm volatile("ldmatrix.sync.aligned.m8n8.x2.shared.b16 {%0,%1}, [%2];"
                                 : "=r"(b0), "=r"(b1) : "r"(baddr));
                    asm volatile("mma.sync.aligned.m16n8k16.row.col.f32.bf16.bf16.f32 "
                                 "{%0,%1,%2,%3}, {%4,%5,%6,%7}, {%8,%9}, {%0,%1,%2,%3};"
                                 : "+f"(acc[nt][0]), "+f"(acc[nt][1]),
                                   "+f"(acc[nt][2]), "+f"(acc[nt][3])
                                 : "r"(a0), "r"(a1), "r"(a2), "r"(a3), "r"(b0), "r"(b1));
                }
            }
        }

        // ---- bias + partial LN stats over this warp's 64 cols ----
        float sA = 0.f, qA = 0.f, sB = 0.f, qB = 0.f;
#pragma unroll
        for (int nt = 0; nt < 8; nt++) {
            int col = ch * 64 + nt * 8 + qlane * 2;
            float b0 = sbi[col], b1 = sbi[col + 1];
            acc[nt][0] += b0; acc[nt][1] += b1;
            acc[nt][2] += b0; acc[nt][3] += b1;
            sA += acc[nt][0] + acc[nt][1];
            qA += acc[nt][0] * acc[nt][0] + acc[nt][1] * acc[nt][1];
            sB += acc[nt][2] + acc[nt][3];
            qB += acc[nt][2] * acc[nt][2] + acc[nt][3] * acc[nt][3];
        }
        sA += __shfl_xor_sync(0xFFFFFFFFu, sA, 1); sA += __shfl_xor_sync(0xFFFFFFFFu, sA, 2);
        qA += __shfl_xor_sync(0xFFFFFFFFu, qA, 1); qA += __shfl_xor_sync(0xFFFFFFFFu, qA, 2);
        sB += __shfl_xor_sync(0xFFFFFFFFu, sB, 1); sB += __shfl_xor_sync(0xFFFFFFFFu, sB, 2);
        qB += __shfl_xor_sync(0xFFFFFFFFu, qB, 1); qB += __shfl_xor_sync(0xFFFFFFFFu, qB, 2);

        if (qlane == 0) {
            s_s[ch * 64 + rowA] = sA;  s_q[ch * 64 + rowA] = qA;
            s_s[ch * 64 + rowA + 8] = sB;  s_q[ch * 64 + rowA + 8] = qB;
        }
        __syncthreads();

        // ---- combine halves, LN + ReLU, store ----
        {
            float SAc = s_s[rowA] + s_s[64 + rowA];
            float QAc = s_q[rowA] + s_q[64 + rowA];
            float SBc = s_s[rowA + 8] + s_s[64 + rowA + 8];
            float QBc = s_q[rowA + 8] + s_q[64 + rowA + 8];
            float muA = SAc * (1.0f / 128.0f);
            float rsA = rsqrtf(QAc * (1.0f / 128.0f) - muA * muA + LN_EPS);
            float muB = SBc * (1.0f / 128.0f);
            float rsB = rsqrtf(QBc * (1.0f / 128.0f) - muB * muB + LN_EPS);

            const int gA = base_row + rowA;
            const int gB = gA + 8;
#pragma unroll
            for (int nt = 0; nt < 8; nt++) {
                int col = ch * 64 + nt * 8 + qlane * 2;
                float g0 = sga[col], g1 = sga[col + 1];
                float e0 = sbe[col], e1 = sbe[col + 1];
                if (gA < N) {
                    float2 o;
                    o.x = fmaxf((acc[nt][0] - muA) * rsA * g0 + e0, 0.f);
                    o.y = fmaxf((acc[nt][1] - muA) * rsA * g1 + e1, 0.f);
                    *reinterpret_cast<float2*>(out + (size_t)gA * 128 + col) = o;
                }
                if (gB < N) {
                    float2 o;
                    o.x = fmaxf((acc[nt][2] - muB) * rsB * g0 + e0, 0.f);
                    o.y = fmaxf((acc[nt][3] - muB) * rsB * g1 + e1, 0.f);
                    *reinterpret_cast<float2*>(out + (size_t)gB * 128 + col) = o;
                }
            }
        }
    }
}

// ---------------------------------------------------------------------------
extern "C" void kernel_launch(void* const* d_in, const int* in_sizes, int n_in,
                              void* d_out, int out_size) {
    const float* h     = (const float*)d_in[0];
    const int*   ei    = (const int*)d_in[1];
    const float* W     = (const float*)d_in[2];
    const float* bias  = (const float*)d_in[3];
    const float* gamma = (const float*)d_in[4];
    const float* beta  = (const float*)d_in[5];
    float*       out   = (float*)d_out;

    const int N = in_sizes[0] / D;
    const int E = in_sizes[1] / 2;
    const int* src = ei;
    const int* dst = ei + E;

    static bool attr_set = false;
    if (!attr_set) {
        cudaFuncSetAttribute(k_mma_gemm, cudaFuncAttributeMaxDynamicSharedMemorySize, SMEM_TOTAL);
        attr_set = true;
    }

    int n4 = N * D4;
    k_init_agg<<<(n4 + 255) / 256, 256>>>(reinterpret_cast<const float4*>(h), n4);
    k_prep_w<<<64, 256>>>(W);
    k_scatter_v4<<<(E + 7) / 8, 256>>>(reinterpret_cast<const float4*>(h), src, dst, E);
    k_mma_gemm<<<GEMM_CTAS, 256, SMEM_TOTAL>>>(bias, gamma, beta, out, N);
}